// round 8
// baseline (speedup 1.0000x reference)
#include <cuda_runtime.h>

// Inverse 2D DWT, single level. (4,64,256,256) f32 x4 subbands -> (4,64,512,512) f32.
// Warp-autonomous with cp.async staging: one warp owns a 64-col strip x 32 rows.
// Input rows stream GMEM -> per-warp SMEM ring (8 slots) via cp.async, staged 7 rows
// ahead, synchronized with cp.async.wait_group only (no __syncthreads/__syncwarp:
// each lane reads only its own staged copies; cross-lane exchange uses shuffles).
// Halo columns (strip edges, W-reflection baked in) are staged into the ring too.
// Column pass f32x2 from smem; row pass via shuffles; float4 streaming stores.

#define HH 256
#define WW 256
#define RW 32
#define NT 128
#define SLOTF 68                 // floats per (slot,subband): [1]=Lhalo [2..65]=owned [66]=Rhalo
#define SLOTSTRIDE (4 * SLOTF)   // floats per slot (4 subbands)

typedef unsigned long long u64;

__device__ __forceinline__ u64 pk(float lo, float hi) {
    u64 r; asm("mov.b64 %0, {%1, %2};" : "=l"(r) : "f"(lo), "f"(hi)); return r;
}
__device__ __forceinline__ void unpk(u64 v, float& lo, float& hi) {
    asm("mov.b64 {%0, %1}, %2;" : "=f"(lo), "=f"(hi) : "l"(v));
}
__device__ __forceinline__ float lof(u64 v) { float a, b; unpk(v, a, b); return a; }
__device__ __forceinline__ float hif(u64 v) { float a, b; unpk(v, a, b); return b; }
__device__ __forceinline__ u64 ffma2(u64 a, u64 b, u64 c) {
    u64 d; asm("fma.rn.f32x2 %0, %1, %2, %3;" : "=l"(d) : "l"(a), "l"(b), "l"(c)); return d;
}
__device__ __forceinline__ u64 fmul2(u64 a, u64 b) {
    u64 d; asm("mul.rn.f32x2 %0, %1, %2;" : "=l"(d) : "l"(a), "l"(b)); return d;
}
__device__ __forceinline__ int reflH(int i) {
    return i < 0 ? -i : (i >= HH ? 2 * HH - 2 - i : i);
}
__device__ __forceinline__ float shup(float v) { return __shfl_up_sync(0xffffffffu, v, 1); }
__device__ __forceinline__ float shdn(float v) { return __shfl_down_sync(0xffffffffu, v, 1); }

__global__ __launch_bounds__(NT, 5)
void idwt2d(const float* __restrict__ ss, const float* __restrict__ sd,
            const float* __restrict__ ds, const float* __restrict__ dd,
            const float* __restrict__ hf, const float* __restrict__ gf,
            float* __restrict__ out)
{
    // per-warp ring: [warp][slot][subband][col]
    __shared__ __align__(16) float ring[NT / 32][8][4][SLOTF];

    const int lane = threadIdx.x & 31;
    const int wid  = threadIdx.x >> 5;
    const int bc   = blockIdx.z;
    const int r0   = blockIdx.y * RW;
    const int wb   = 64 * wid;

    const size_t base = (size_t)bc * (HH * WW);
    const float* gsub[4] = { ss + base + wb, sd + base + wb,
                             ds + base + wb, dd + base + wb };
    float* __restrict__ pout = out + (size_t)bc * (4 * HH * WW) + 2 * (wb + 2 * lane);

    // halo columns relative to wb (W-reflection baked in)
    const int hl = (wb > 0) ? -1 : 1;
    const int hr = (wb + 64 < WW) ? 64 : 62;
    const int hofs = (lane == 31) ? hr : hl;
    const int hdst = (lane == 31) ? 66 : 1;
    const bool dohalo = (lane == 0) || (lane == 31);

    const unsigned smw = (unsigned)__cvta_generic_to_shared(&ring[wid][0][0][0]);
    const float* fring = &ring[wid][0][0][0];

    u64 H0, H1, H2, H3, H4, H5, G0, G1, G2, G3, G4, G5;
    {
        const float a0 = hf[0], a1 = hf[1], a2 = hf[2], a3 = hf[3], a4 = hf[4], a5 = hf[5];
        const float b0 = gf[0], b1 = gf[1], b2 = gf[2], b3 = gf[3], b4 = gf[4], b5 = gf[5];
        H0 = pk(a0, a0); H1 = pk(a1, a1); H2 = pk(a2, a2);
        H3 = pk(a3, a3); H4 = pk(a4, a4); H5 = pk(a5, a5);
        G0 = pk(b0, b0); G1 = pk(b1, b1); G2 = pk(b2, b2);
        G3 = pk(b3, b3); G4 = pk(b4, b4); G5 = pk(b5, b5);
    }

    // stage window-row j (absolute input row reflH(r0-1+j)) into slot j&7
    auto stage_row = [&](int j) {
        const int gr = reflH(r0 - 1 + j);
        const unsigned sb = smw + ((j & 7) * SLOTSTRIDE) * 4u;
        #pragma unroll
        for (int p = 0; p < 4; ++p) {
            const float* g = gsub[p] + (size_t)gr * WW;
            const unsigned dsto = sb + (unsigned)(p * SLOTF + 2 + 2 * lane) * 4u;
            asm volatile("cp.async.ca.shared.global [%0], [%1], 8;"
                         :: "r"(dsto), "l"(g + 2 * lane) : "memory");
            if (dohalo) {
                const unsigned dsth = sb + (unsigned)(p * SLOTF + hdst) * 4u;
                asm volatile("cp.async.ca.shared.global [%0], [%1], 4;"
                             :: "r"(dsth), "l"(g + hofs) : "memory");
            }
        }
    };

    // prime 7 rows (window rows 0..6), one commit group each
    #pragma unroll
    for (int j = 0; j < 7; ++j) {
        stage_row(j);
        asm volatile("cp.async.commit_group;" ::: "memory");
    }

    #pragma unroll 2
    for (int i = 0; i < RW; ++i) {
        // stage window row i+7 (writes slot (i-1)&7 -> never clashes with reads i..i+2)
        if (i + 7 < RW + 2) stage_row(i + 7);
        asm volatile("cp.async.commit_group;" ::: "memory");
        // groups issued = i+8; pending<=5 => rows 0..i+2 complete
        asm volatile("cp.async.wait_group 5;" ::: "memory");

        const float* fa = fring + ((i    ) & 7) * SLOTSTRIDE;
        const float* fb = fring + ((i + 1) & 7) * SLOTSTRIDE;
        const float* fc = fring + ((i + 2) & 7) * SLOTSTRIDE;
        const int oo = 2 + 2 * lane;

        const u64 S0 = *(const u64*)(fa + 0 * SLOTF + oo);
        const u64 S1 = *(const u64*)(fb + 0 * SLOTF + oo);
        const u64 S2 = *(const u64*)(fc + 0 * SLOTF + oo);
        const u64 T0 = *(const u64*)(fa + 1 * SLOTF + oo);
        const u64 T1 = *(const u64*)(fb + 1 * SLOTF + oo);
        const u64 T2 = *(const u64*)(fc + 1 * SLOTF + oo);
        const u64 U0 = *(const u64*)(fa + 2 * SLOTF + oo);
        const u64 U1 = *(const u64*)(fb + 2 * SLOTF + oo);
        const u64 U2 = *(const u64*)(fc + 2 * SLOTF + oo);
        const u64 V0 = *(const u64*)(fa + 3 * SLOTF + oo);
        const u64 V1 = *(const u64*)(fb + 3 * SLOTF + oo);
        const u64 V2 = *(const u64*)(fc + 3 * SLOTF + oo);

        const float hs0 = fa[0 * SLOTF + hdst], hs1 = fb[0 * SLOTF + hdst], hs2 = fc[0 * SLOTF + hdst];
        const float ht0 = fa[1 * SLOTF + hdst], ht1 = fb[1 * SLOTF + hdst], ht2 = fc[1 * SLOTF + hdst];
        const float hu0 = fa[2 * SLOTF + hdst], hu1 = fb[2 * SLOTF + hdst], hu2 = fc[2 * SLOTF + hdst];
        const float hv0 = fa[3 * SLOTF + hdst], hv1 = fb[3 * SLOTF + hdst], hv2 = fc[3 * SLOTF + hdst];

        // ---- column pass (f32x2, both owned columns) ----
        const u64 A0 = ffma2(H4, S0, ffma2(H2, S1, ffma2(H0, S2,
                       ffma2(G4, T0, ffma2(G2, T1, fmul2(G0, T2))))));
        const u64 A1 = ffma2(H5, S0, ffma2(H3, S1, ffma2(H1, S2,
                       ffma2(G5, T0, ffma2(G3, T1, fmul2(G1, T2))))));
        const u64 A2 = ffma2(H4, U0, ffma2(H2, U1, ffma2(H0, U2,
                       ffma2(G4, V0, ffma2(G2, V1, fmul2(G0, V2))))));
        const u64 A3 = ffma2(H5, U0, ffma2(H3, U1, ffma2(H1, U2,
                       ffma2(G5, V0, ffma2(G3, V1, fmul2(G1, V2))))));

        // ---- halo column pass (packed: lo = s-side, hi = d-side) ----
        const u64 P0 = pk(hs0, hu0), Q0 = pk(ht0, hv0);
        const u64 P1 = pk(hs1, hu1), Q1 = pk(ht1, hv1);
        const u64 P2 = pk(hs2, hu2), Q2 = pk(ht2, hv2);
        const u64 B02 = ffma2(H4, P0, ffma2(H2, P1, ffma2(H0, P2,
                        ffma2(G4, Q0, ffma2(G2, Q1, fmul2(G0, Q2))))));  // (b0,b2)
        const u64 B13 = ffma2(H5, P0, ffma2(H3, P1, ffma2(H1, P2,
                        ffma2(G5, Q0, ffma2(G3, Q1, fmul2(G1, Q2))))));  // (b1,b3)

        // ---- row pass ----
        const int r = r0 + i;
        #pragma unroll
        for (int py = 0; py < 2; ++py) {
            const u64 X = py ? A1 : A0;
            const u64 Y = py ? A3 : A2;
            const u64 B = py ? B13 : B02;
            const float hx = lof(B), hy = hif(B);

            float xm = shup(hif(X)); if (lane == 0)  xm = hx;   // v[c-1]
            float xp = shdn(lof(X)); if (lane == 31) xp = hx;   // v[c+2]
            float ym = shup(hif(Y)); if (lane == 0)  ym = hy;
            float yp = shdn(lof(Y)); if (lane == 31) yp = hy;

            const u64 AX = pk(xm, lof(X)), CX = pk(hif(X), xp);
            const u64 AY = pk(ym, lof(Y)), CY = pk(hif(Y), yp);

            const u64 pe = ffma2(H4, AX, ffma2(H2, X, ffma2(H0, CX,
                           ffma2(G4, AY, ffma2(G2, Y, fmul2(G0, CY))))));
            const u64 po = ffma2(H5, AX, ffma2(H3, X, ffma2(H1, CX,
                           ffma2(G5, AY, ffma2(G3, Y, fmul2(G1, CY))))));

            float e0, e1, f0, f1;
            unpk(pe, e0, e1); unpk(po, f0, f1);
            __stcs((float4*)(pout + (size_t)(2 * r + py) * (2 * WW)),
                   make_float4(e0, f0, e1, f1));
        }
    }
}

extern "C" void kernel_launch(void* const* d_in, const int* in_sizes, int n_in,
                              void* d_out, int out_size) {
    const float* ss = (const float*)d_in[0];
    const float* sd = (const float*)d_in[1];
    const float* ds = (const float*)d_in[2];
    const float* dd = (const float*)d_in[3];
    const float* h  = (const float*)d_in[4];
    const float* g  = (const float*)d_in[5];
    float* out = (float*)d_out;

    dim3 grid(1, HH / RW, 4 * 64);   // (1, 8, 256) = 2048 blocks x 4 warps
    idwt2d<<<grid, NT>>>(ss, sd, ds, dd, h, g, out);
}

// round 9
// speedup vs baseline: 1.2176x; 1.2176x over previous
#include <cuda_runtime.h>

// Inverse 2D DWT, single level. (4,64,256,256) f32 x4 subbands -> (4,64,512,512) f32.
// Warp-autonomous, LDG.128 edition: one warp owns a 128-col strip x RW rows; each
// lane owns 4 adjacent columns (one ulonglong2 = 2 f32x2 per subband-row).
//  - Rolling 3-row window; next row loaded right after the column pass (hidden
//    under the row pass). Reads are 512B contiguous per warp-request, writes 1KB.
//  - W-edge reflection is in-lane (v[-1]=v[1], v[256]=v[254] are owned columns);
//    only ONE interior halo column per strip (col 128 / col 127), scalar loads.
//  - All math is packed fp32x2 (FFMA2). No smem, no barriers. Full unroll.

#define HH 256
#define WW 256
#define RW 16
#define NT 128

typedef unsigned long long u64;

__device__ __forceinline__ u64 pk(float lo, float hi) {
    u64 r; asm("mov.b64 %0, {%1, %2};" : "=l"(r) : "f"(lo), "f"(hi)); return r;
}
__device__ __forceinline__ void unpk(u64 v, float& lo, float& hi) {
    asm("mov.b64 {%0, %1}, %2;" : "=f"(lo), "=f"(hi) : "l"(v));
}
__device__ __forceinline__ float lof(u64 v) { float a, b; unpk(v, a, b); return a; }
__device__ __forceinline__ float hif(u64 v) { float a, b; unpk(v, a, b); return b; }
__device__ __forceinline__ u64 ffma2(u64 a, u64 b, u64 c) {
    u64 d; asm("fma.rn.f32x2 %0, %1, %2, %3;" : "=l"(d) : "l"(a), "l"(b), "l"(c)); return d;
}
__device__ __forceinline__ u64 fmul2(u64 a, u64 b) {
    u64 d; asm("mul.rn.f32x2 %0, %1, %2;" : "=l"(d) : "l"(a), "l"(b)); return d;
}
__device__ __forceinline__ int reflH(int i) {
    return i < 0 ? -i : (i >= HH ? 2 * HH - 2 - i : i);
}
__device__ __forceinline__ float shup(float v) { return __shfl_up_sync(0xffffffffu, v, 1); }
__device__ __forceinline__ float shdn(float v) { return __shfl_down_sync(0xffffffffu, v, 1); }
__device__ __forceinline__ ulonglong2 ldg4(const float* __restrict__ p, int row) {
    return __ldcs((const ulonglong2*)(p + (size_t)row * WW));
}
__device__ __forceinline__ float ldg1(const float* __restrict__ p, int row, int dq) {
    return __ldcs(p + (size_t)row * WW + dq);
}

__global__ __launch_bounds__(NT, 4)
void idwt2d(const float* __restrict__ ss, const float* __restrict__ sd,
            const float* __restrict__ ds, const float* __restrict__ dd,
            const float* __restrict__ hf, const float* __restrict__ gf,
            float* __restrict__ out)
{
    const int lane  = threadIdx.x & 31;
    const int wid   = threadIdx.x >> 5;
    const int strip = wid & 1;                        // 0: cols 0-127, 1: cols 128-255
    const int bc    = blockIdx.z;
    const int r0    = blockIdx.y * (2 * RW) + (wid >> 1) * RW;
    const int c     = strip * 128 + 4 * lane;         // first of 4 owned columns
    const int dq    = (strip ? 127 : 128) - c;        // interior halo column offset

    const size_t base = (size_t)bc * (HH * WW);
    const float* __restrict__ pss = ss + base + c;
    const float* __restrict__ psd = sd + base + c;
    const float* __restrict__ pds = ds + base + c;
    const float* __restrict__ pdd = dd + base + c;
    float* __restrict__ pout = out + (size_t)bc * (4 * HH * WW) + 2 * c;

    u64 H0, H1, H2, H3, H4, H5, G0, G1, G2, G3, G4, G5;
    {
        const float a0 = hf[0], a1 = hf[1], a2 = hf[2], a3 = hf[3], a4 = hf[4], a5 = hf[5];
        const float b0 = gf[0], b1 = gf[1], b2 = gf[2], b3 = gf[3], b4 = gf[4], b5 = gf[5];
        H0 = pk(a0, a0); H1 = pk(a1, a1); H2 = pk(a2, a2);
        H3 = pk(a3, a3); H4 = pk(a4, a4); H5 = pk(a5, a5);
        G0 = pk(b0, b0); G1 = pk(b1, b1); G2 = pk(b2, b2);
        G3 = pk(b3, b3); G4 = pk(b4, b4); G5 = pk(b5, b5);
    }

    // 3-row window: a = row r-1, b = row r, c-slot = row r+1
    ulonglong2 Sa, Sb, Sc, Ta, Tb, Tc, Ua, Ub, Uc, Va, Vb, Vc;
    float hsa, hsb, hsc, hta, htb, htc, hua, hub, huc, hva, hvb, hvc;
    {
        const int rm = reflH(r0 - 1);
        Sa = ldg4(pss, rm); Ta = ldg4(psd, rm); Ua = ldg4(pds, rm); Va = ldg4(pdd, rm);
        hsa = ldg1(pss, rm, dq); hta = ldg1(psd, rm, dq);
        hua = ldg1(pds, rm, dq); hva = ldg1(pdd, rm, dq);
        Sb = ldg4(pss, r0); Tb = ldg4(psd, r0); Ub = ldg4(pds, r0); Vb = ldg4(pdd, r0);
        hsb = ldg1(pss, r0, dq); htb = ldg1(psd, r0, dq);
        hub = ldg1(pds, r0, dq); hvb = ldg1(pdd, r0, dq);
        Sc = ldg4(pss, r0 + 1); Tc = ldg4(psd, r0 + 1); Uc = ldg4(pds, r0 + 1); Vc = ldg4(pdd, r0 + 1);
        hsc = ldg1(pss, r0 + 1, dq); htc = ldg1(psd, r0 + 1, dq);
        huc = ldg1(pds, r0 + 1, dq); hvc = ldg1(pdd, r0 + 1, dq);
    }

    #pragma unroll
    for (int i = 0; i < RW; ++i) {
        const int r = r0 + i;

        // ---- column pass (4 arrays x 2 u64 halves) ----
        const u64 A0x = ffma2(H4, Sa.x, ffma2(H2, Sb.x, ffma2(H0, Sc.x,
                        ffma2(G4, Ta.x, ffma2(G2, Tb.x, fmul2(G0, Tc.x))))));
        const u64 A0y = ffma2(H4, Sa.y, ffma2(H2, Sb.y, ffma2(H0, Sc.y,
                        ffma2(G4, Ta.y, ffma2(G2, Tb.y, fmul2(G0, Tc.y))))));
        const u64 A1x = ffma2(H5, Sa.x, ffma2(H3, Sb.x, ffma2(H1, Sc.x,
                        ffma2(G5, Ta.x, ffma2(G3, Tb.x, fmul2(G1, Tc.x))))));
        const u64 A1y = ffma2(H5, Sa.y, ffma2(H3, Sb.y, ffma2(H1, Sc.y,
                        ffma2(G5, Ta.y, ffma2(G3, Tb.y, fmul2(G1, Tc.y))))));
        const u64 A2x = ffma2(H4, Ua.x, ffma2(H2, Ub.x, ffma2(H0, Uc.x,
                        ffma2(G4, Va.x, ffma2(G2, Vb.x, fmul2(G0, Vc.x))))));
        const u64 A2y = ffma2(H4, Ua.y, ffma2(H2, Ub.y, ffma2(H0, Uc.y,
                        ffma2(G4, Va.y, ffma2(G2, Vb.y, fmul2(G0, Vc.y))))));
        const u64 A3x = ffma2(H5, Ua.x, ffma2(H3, Ub.x, ffma2(H1, Uc.x,
                        ffma2(G5, Va.x, ffma2(G3, Vb.x, fmul2(G1, Vc.x))))));
        const u64 A3y = ffma2(H5, Ua.y, ffma2(H3, Ub.y, ffma2(H1, Uc.y,
                        ffma2(G5, Va.y, ffma2(G3, Vb.y, fmul2(G1, Vc.y))))));

        // halo column pass (packed pairwise: lo = s-side, hi = d-side)
        const u64 P0 = pk(hsa, hua), Q0 = pk(hta, hva);
        const u64 P1 = pk(hsb, hub), Q1 = pk(htb, hvb);
        const u64 P2 = pk(hsc, huc), Q2 = pk(htc, hvc);
        const u64 B02 = ffma2(H4, P0, ffma2(H2, P1, ffma2(H0, P2,
                        ffma2(G4, Q0, ffma2(G2, Q1, fmul2(G0, Q2))))));   // (b0, b2)
        const u64 B13 = ffma2(H5, P0, ffma2(H3, P1, ffma2(H1, P2,
                        ffma2(G5, Q0, ffma2(G3, Q1, fmul2(G1, Q2))))));   // (b1, b3)

        // ---- roll window + load next row (consumed next iteration) ----
        Sa = Sb; Sb = Sc; Ta = Tb; Tb = Tc;
        Ua = Ub; Ub = Uc; Va = Vb; Vb = Vc;
        hsa = hsb; hsb = hsc; hta = htb; htb = htc;
        hua = hub; hub = huc; hva = hvb; hvb = hvc;
        if (i != RW - 1) {
            const int rn = reflH(r + 2);
            Sc = ldg4(pss, rn); Tc = ldg4(psd, rn);
            Uc = ldg4(pds, rn); Vc = ldg4(pdd, rn);
            hsc = ldg1(pss, rn, dq); htc = ldg1(psd, rn, dq);
            huc = ldg1(pds, rn, dq); hvc = ldg1(pdd, rn, dq);
        }

        // ---- row pass ----
        #pragma unroll
        for (int py = 0; py < 2; ++py) {
            const u64 Xa = py ? A1x : A0x, Xb = py ? A1y : A0y;   // sv: {x0,x1},{x2,x3}
            const u64 Ya = py ? A3x : A2x, Yb = py ? A3y : A2y;   // dv
            const u64 B  = py ? B13 : B02;
            const float hx = lof(B), hy = hif(B);

            // v[c-1]: from lane-1's x3; strip0 lane0 -> in-lane v[1], strip1 lane0 -> halo
            float xm1 = shup(hif(Xb)); if (lane == 0)  xm1 = strip ? hx : hif(Xa);
            // v[c+4]: from lane+1's x0; strip0 lane31 -> halo, strip1 lane31 -> in-lane v[254]
            float xp4 = shdn(lof(Xa)); if (lane == 31) xp4 = strip ? lof(Xb) : hx;
            float ym1 = shup(hif(Yb)); if (lane == 0)  ym1 = strip ? hy : hif(Ya);
            float yp4 = shdn(lof(Ya)); if (lane == 31) yp4 = strip ? lof(Yb) : hy;

            const u64 AX = pk(xm1, lof(Xa));        // {x-1, x0}
            const u64 MX = pk(hif(Xa), lof(Xb));    // {x1, x2}  (C of pair01 == A of pair23)
            const u64 CX = pk(hif(Xb), xp4);        // {x3, x4}
            const u64 AY = pk(ym1, lof(Ya));
            const u64 MY = pk(hif(Ya), lof(Yb));
            const u64 CY = pk(hif(Yb), yp4);

            const u64 pe01 = ffma2(H4, AX, ffma2(H2, Xa, ffma2(H0, MX,
                             ffma2(G4, AY, ffma2(G2, Ya, fmul2(G0, MY))))));
            const u64 po01 = ffma2(H5, AX, ffma2(H3, Xa, ffma2(H1, MX,
                             ffma2(G5, AY, ffma2(G3, Ya, fmul2(G1, MY))))));
            const u64 pe23 = ffma2(H4, MX, ffma2(H2, Xb, ffma2(H0, CX,
                             ffma2(G4, MY, ffma2(G2, Yb, fmul2(G0, CY))))));
            const u64 po23 = ffma2(H5, MX, ffma2(H3, Xb, ffma2(H1, CX,
                             ffma2(G5, MY, ffma2(G3, Yb, fmul2(G1, CY))))));

            float e0, e1, f0, f1;
            float* __restrict__ prow = pout + (size_t)(2 * r + py) * (2 * WW);
            unpk(pe01, e0, e1); unpk(po01, f0, f1);
            __stcs((float4*)prow, make_float4(e0, f0, e1, f1));
            unpk(pe23, e0, e1); unpk(po23, f0, f1);
            __stcs((float4*)(prow + 4), make_float4(e0, f0, e1, f1));
        }
    }
}

extern "C" void kernel_launch(void* const* d_in, const int* in_sizes, int n_in,
                              void* d_out, int out_size) {
    const float* ss = (const float*)d_in[0];
    const float* sd = (const float*)d_in[1];
    const float* ds = (const float*)d_in[2];
    const float* dd = (const float*)d_in[3];
    const float* h  = (const float*)d_in[4];
    const float* g  = (const float*)d_in[5];
    float* out = (float*)d_out;

    dim3 grid(1, HH / (2 * RW), 4 * 64);   // (1, 8, 256) = 2048 blocks x 4 warps
    idwt2d<<<grid, NT>>>(ss, sd, ds, dd, h, g, out);
}